// round 3
// baseline (speedup 1.0000x reference)
#include <cuda_runtime.h>
#include <cuda_bf16.h>
#include <cstdint>

#define H_FEATS 128
#define D2 256
#define LN_EPS 1e-5f
#define MAX_NODES 262144

// Scratch (device globals: allowed; no dynamic allocation)
__device__ float4 g_node_tab[MAX_NODES];   // x=sum, y=sumsq, z=dot(gW[0:128]), w=dot(gW[128:256])
__device__ float  g_gW[D2];
__device__ float  g_Sgw;
__device__ float  g_C;

// ---------------------------------------------------------------------------
// Kernel 1: tiny prep — gW = gamma*W, Sgw = sum(gW), C = sum(beta*W) + b
// ---------------------------------------------------------------------------
__global__ void prep_kernel(const float* __restrict__ gamma,
                            const float* __restrict__ beta,
                            const float* __restrict__ W,
                            const float* __restrict__ b) {
    __shared__ float s1[D2];
    __shared__ float s2[D2];
    int i = threadIdx.x;  // 256 threads
    float w  = W[i];
    float gw = gamma[i] * w;
    g_gW[i] = gw;
    s1[i] = gw;
    s2[i] = beta[i] * w;
    __syncthreads();
    #pragma unroll
    for (int off = 128; off > 0; off >>= 1) {
        if (i < off) { s1[i] += s1[i + off]; s2[i] += s2[i + off]; }
        __syncthreads();
    }
    if (i == 0) {
        g_Sgw = s1[0];
        g_C   = s2[0] + b[0];
    }
}

// ---------------------------------------------------------------------------
// Kernel 2: per-node stats. One warp per node, float4 per lane (128 floats).
// ---------------------------------------------------------------------------
__global__ void node_stats_kernel(const float* __restrict__ h, int n_nodes) {
    int gtid = blockIdx.x * blockDim.x + threadIdx.x;
    int node = gtid >> 5;
    int lane = threadIdx.x & 31;
    if (node >= n_nodes) return;

    const float4* row = reinterpret_cast<const float4*>(h + (size_t)node * H_FEATS);
    float4 v = __ldg(row + lane);

    const float4* gw  = reinterpret_cast<const float4*>(g_gW);
    float4 g0 = gw[lane];        // gW[lane*4 .. +3]     (src half)
    float4 g1 = gw[lane + 32];   // gW[128 + lane*4 ..]  (dst half)

    float s1 = v.x + v.y + v.z + v.w;
    float s2 = v.x*v.x + v.y*v.y + v.z*v.z + v.w*v.w;
    float ds = v.x*g0.x + v.y*g0.y + v.z*g0.z + v.w*g0.w;
    float dd = v.x*g1.x + v.y*g1.y + v.z*g1.z + v.w*g1.w;

    #pragma unroll
    for (int off = 16; off > 0; off >>= 1) {
        s1 += __shfl_down_sync(0xFFFFFFFFu, s1, off);
        s2 += __shfl_down_sync(0xFFFFFFFFu, s2, off);
        ds += __shfl_down_sync(0xFFFFFFFFu, ds, off);
        dd += __shfl_down_sync(0xFFFFFFFFu, dd, off);
    }
    if (lane == 0) {
        g_node_tab[node] = make_float4(s1, s2, ds, dd);
    }
}

// ---------------------------------------------------------------------------
// Kernel 3: per-edge score. Table gathers land in L2 (1.6 MB table).
// ---------------------------------------------------------------------------
__global__ void edge_score_kernel(const int* __restrict__ src,
                                  const int* __restrict__ dst,
                                  float* __restrict__ out, int n_edges) {
    int i = blockIdx.x * blockDim.x + threadIdx.x;
    if (i >= n_edges) return;

    int si = src[i];
    int di = dst[i];
    float4 a = g_node_tab[si];
    float4 c = g_node_tab[di];

    const float inv = 1.0f / (float)D2;
    float sum   = a.x + c.x;
    float sumsq = a.y + c.y;
    float dot   = a.z + c.w;   // src uses first-half gW dot, dst uses second-half

    float mu   = sum * inv;
    float var  = fmaf(-mu, mu, sumsq * inv);
    float rstd = rsqrtf(var + LN_EPS);

    out[i] = fmaf(rstd, fmaf(-mu, g_Sgw, dot), g_C);
}

// ---------------------------------------------------------------------------
// Launch
// Inputs: 0=h [N*128] f32, 1=src [E] i32, 2=dst [E] i32,
//         3=ln_gamma [256] f32, 4=ln_beta [256] f32, 5=W [256] f32, 6=b [1] f32
// Output: [E] f32
// ---------------------------------------------------------------------------
extern "C" void kernel_launch(void* const* d_in, const int* in_sizes, int n_in,
                              void* d_out, int out_size) {
    const float* h     = (const float*)d_in[0];
    const int*   src   = (const int*)d_in[1];
    const int*   dst   = (const int*)d_in[2];
    const float* gamma = (const float*)d_in[3];
    const float* beta  = (const float*)d_in[4];
    const float* W     = (const float*)d_in[5];
    const float* b     = (const float*)d_in[6];
    float* out = (float*)d_out;

    int n_nodes = in_sizes[0] / H_FEATS;
    int n_edges = in_sizes[1];

    prep_kernel<<<1, D2>>>(gamma, beta, W, b);

    // one warp per node, 8 warps per block
    int nodes_per_block = 256 / 32;
    int nblocks = (n_nodes + nodes_per_block - 1) / nodes_per_block;
    node_stats_kernel<<<nblocks, 256>>>(h, n_nodes);

    int eblocks = (n_edges + 255) / 256;
    edge_score_kernel<<<eblocks, 256>>>(src, dst, out, n_edges);
}